// round 4
// baseline (speedup 1.0000x reference)
#include <cuda_runtime.h>
#include <cuda_bf16.h>
#include <cstdint>

#define NNODES 100000
#define NP     100352            // multiple of 1024 and 128
#define H      128
#define EMAX   1600000

// ---------------- device scratch ----------------
__device__ float g_X[4][(size_t)NP * H];
__device__ float g_agg[(size_t)NP * H];
__device__ int   g_deg[NP];
__device__ float g_invdeg[NP];
__device__ int   g_rowstart[NP + 1];
__device__ int   g_cursor[NP];
__device__ int   g_csrsrc[EMAX];
__device__ uint8_t g_wfrag[5 * 131072];               // 3 layers + 2 JK phases

// ---------------- CSR build ----------------
__global__ void k_zero_deg() {
    int i = blockIdx.x * blockDim.x + threadIdx.x;
    if (i < NP) g_deg[i] = 0;
}
__global__ void k_hist(const int* __restrict__ dst, int E) {
    int i = blockIdx.x * blockDim.x + threadIdx.x;
    if (i < E) atomicAdd(&g_deg[dst[i]], 1);
}
__global__ void k_scan() {
    __shared__ int warp_tot[32];
    int t = threadIdx.x, lane = t & 31, wid = t >> 5;
    int running = 0;
    for (int base = 0; base < NP; base += 1024) {
        int v = g_deg[base + t];
        int x = v;
        #pragma unroll
        for (int d = 1; d < 32; d <<= 1) {
            int y = __shfl_up_sync(0xffffffffu, x, d);
            if (lane >= d) x += y;
        }
        if (lane == 31) warp_tot[wid] = x;
        __syncthreads();
        if (wid == 0) {
            int y = warp_tot[lane];
            #pragma unroll
            for (int d = 1; d < 32; d <<= 1) {
                int z = __shfl_up_sync(0xffffffffu, y, d);
                if (lane >= d) y += z;
            }
            warp_tot[lane] = y;
        }
        __syncthreads();
        int warp_off = (wid == 0) ? 0 : warp_tot[wid - 1];
        g_rowstart[base + t] = running + warp_off + x - v;
        int block_tot = warp_tot[31];
        __syncthreads();
        running += block_tot;
        g_invdeg[base + t] = 1.0f / fmaxf((float)v, 1.0f);
        g_cursor[base + t] = 0;
    }
    if (t == 0) g_rowstart[NP] = running;
}
__global__ void k_fill(const int* __restrict__ src, const int* __restrict__ dst, int E) {
    int i = blockIdx.x * blockDim.x + threadIdx.x;
    if (i < E) {
        int d = dst[i];
        int p = atomicAdd(&g_cursor[d], 1);
        g_csrsrc[g_rowstart[d] + p] = src[i];
    }
}
__global__ void k_copy_emb(const float4* __restrict__ emb) {
    int i = blockIdx.x * blockDim.x + threadIdx.x;
    float4 v = make_float4(0.f, 0.f, 0.f, 0.f);
    if (i < NNODES * (H / 4)) v = emb[i];
    ((float4*)g_X[0])[i] = v;
}

// ---------------- aggregation ----------------
__global__ void k_agg(int layer) {
    int w = (blockIdx.x * blockDim.x + threadIdx.x) >> 5;
    if (w >= NP) return;
    int lane = threadIdx.x & 31;
    const float* __restrict__ xin = g_X[layer];
    int s0 = g_rowstart[w], s1 = g_rowstart[w + 1];
    float ax = 0.f, ay = 0.f, az = 0.f, aw = 0.f;
    int j = s0;
    for (; j + 4 <= s1; j += 4) {
        int i0 = g_csrsrc[j], i1 = g_csrsrc[j + 1], i2 = g_csrsrc[j + 2], i3 = g_csrsrc[j + 3];
        float4 a = ((const float4*)(xin + (size_t)i0 * H))[lane];
        float4 b = ((const float4*)(xin + (size_t)i1 * H))[lane];
        float4 c = ((const float4*)(xin + (size_t)i2 * H))[lane];
        float4 d = ((const float4*)(xin + (size_t)i3 * H))[lane];
        ax += (a.x + b.x) + (c.x + d.x);
        ay += (a.y + b.y) + (c.y + d.y);
        az += (a.z + b.z) + (c.z + d.z);
        aw += (a.w + b.w) + (c.w + d.w);
    }
    for (; j < s1; j++) {
        int i0 = g_csrsrc[j];
        float4 a = ((const float4*)(xin + (size_t)i0 * H))[lane];
        ax += a.x; ay += a.y; az += a.z; aw += a.w;
    }
    float inv = g_invdeg[w];
    float4 o = make_float4(ax * inv, ay * inv, az * inv, aw * inv);
    ((float4*)(g_agg + (size_t)w * H))[lane] = o;
}

// ---------------- bf16 hi/lo split ----------------
__device__ __forceinline__ void split2(float v0, float v1, uint32_t& ph, uint32_t& pl) {
    __nv_bfloat16 h0 = __float2bfloat16(v0), h1 = __float2bfloat16(v1);
    float r0 = v0 - __bfloat162float(h0), r1 = v1 - __bfloat162float(h1);
    __nv_bfloat16 l0 = __float2bfloat16(r0), l1 = __float2bfloat16(r1);
    ph = ((uint32_t)__bfloat16_as_ushort(h1) << 16) | (uint32_t)__bfloat16_as_ushort(h0);
    pl = ((uint32_t)__bfloat16_as_ushort(l1) << 16) | (uint32_t)__bfloat16_as_ushort(l0);
}

// ---------------- W fragment build ----------------
// target t: 0..2 = layer (k<128: Wl, k>=128: Wr), 3..4 = jk phase (jkW cols h*256 + k)
// layout per target: [(nt*16+ks)*32 + lane] * 16B = {bhi0, bhi1, blo0, blo1}
// fragment mapping: n = nt*8 + (lane>>2); k = ks*16 + (lane&3)*2; b0 = W[n][k..k+1], b1 = W[n][k+8..k+9]
__global__ void k_conv_w(const float* __restrict__ Wl, const float* __restrict__ Wr,
                         const float* __restrict__ jkW) {
    int idx = blockIdx.x * blockDim.x + threadIdx.x;
    if (idx >= 5 * 16 * 16 * 32) return;
    int lane = idx & 31;
    int ks = (idx >> 5) & 15;
    int nt = (idx >> 9) & 15;
    int tgt = idx >> 13;
    int g = lane >> 2, tg = lane & 3;
    int n = nt * 8 + g;
    int k = ks * 16 + tg * 2;

    float v[4];
    if (tgt < 3) {
        #pragma unroll
        for (int q = 0; q < 4; q++) {
            int kk = k + (q >> 1) * 8 + (q & 1);
            v[q] = (kk < 128) ? Wl[(size_t)tgt * 16384 + n * 128 + kk]
                              : Wr[(size_t)tgt * 16384 + n * 128 + kk - 128];
        }
    } else {
        int h = tgt - 3;
        #pragma unroll
        for (int q = 0; q < 4; q++) {
            int kk = k + (q >> 1) * 8 + (q & 1);
            v[q] = jkW[(size_t)n * 512 + h * 256 + kk];
        }
    }
    uint32_t bh0, bl0, bh1, bl1;
    split2(v[0], v[1], bh0, bl0);
    split2(v[2], v[3], bh1, bl1);
    uint4 o = make_uint4(bh0, bh1, bl0, bl1);
    *(uint4*)(g_wfrag + (size_t)tgt * 131072 + ((size_t)((nt * 16 + ks) * 32 + lane)) * 16) = o;
}

// ---------------- mma helper ----------------
__device__ __forceinline__ void mma_bf16(float* c, uint4 a, uint32_t b0, uint32_t b1) {
    asm volatile(
        "mma.sync.aligned.m16n8k16.row.col.f32.bf16.bf16.f32 "
        "{%0,%1,%2,%3}, {%4,%5,%6,%7}, {%8,%9}, {%0,%1,%2,%3};"
        : "+f"(c[0]), "+f"(c[1]), "+f"(c[2]), "+f"(c[3])
        : "r"(a.x), "r"(a.y), "r"(a.z), "r"(a.w), "r"(b0), "r"(b1));
}

// ---------------- GEMM with in-kernel A conversion (+ fused LN/ReLU/residual) ----------------
// grid: NP/128 CTAs, 256 threads (8 warps); warp handles 16 rows x 128 cols.
// mode 0..2: layer l (A = concat(agg, X[l]), KS=16, nphase=1, LN epilogue)
// mode 3:    JK      (A = concat(X0..X3),   KS=32, nphase=2, bias-only, guard NNODES)
__global__ void __launch_bounds__(256, 1) k_mma(
    int KS, int wtgt0, int nphase, int do_ln, int layer,
    const float* __restrict__ bias, const float* __restrict__ gamma,
    const float* __restrict__ beta, float* __restrict__ outp)
{
    extern __shared__ uint8_t smem[];
    float* s_bias  = (float*)(smem + 131072);
    float* s_gamma = s_bias + 128;
    float* s_beta  = s_gamma + 128;
    int tid = threadIdx.x, wid = tid >> 5, lane = tid & 31;
    int g = lane >> 2, tg = lane & 3;
    int mt = blockIdx.x * 8 + wid;
    size_t m0 = (size_t)mt * 16 + g, m1 = m0 + 8;

    if (tid < 128) {
        s_bias[tid] = bias[tid];
        if (do_ln) { s_gamma[tid] = gamma[tid]; s_beta[tid] = beta[tid]; }
    }

    float acc[16][4];
    #pragma unroll
    for (int nt = 0; nt < 16; nt++)
        #pragma unroll
        for (int q = 0; q < 4; q++) acc[nt][q] = 0.f;

    for (int ph = 0; ph < nphase; ph++) {
        __syncthreads();
        {   // copy W fragment blob to smem (128KB)
            const uint4* wsrc = (const uint4*)(g_wfrag + (size_t)(wtgt0 + ph) * 131072);
            uint4* wdst = (uint4*)smem;
            #pragma unroll
            for (int i = 0; i < 32; i++) wdst[tid + i * 256] = wsrc[tid + i * 256];
        }
        __syncthreads();
        for (int ksl = 0; ksl < 16; ksl++) {
            int gks = ph * 16 + ksl;
            int gk = gks * 16;
            // A source select + in-register bf16 hi/lo split
            const float* s;
            if (do_ln) s = (gk < 128) ? g_agg : g_X[layer];
            else       s = g_X[gk >> 7];
            int kl = (gk & 127) + tg * 2;
            const float* r0p = s + m0 * H + kl;
            const float* r1p = s + m1 * H + kl;
            float2 p00 = *(const float2*)(r0p);
            float2 p10 = *(const float2*)(r1p);
            float2 p01 = *(const float2*)(r0p + 8);
            float2 p11 = *(const float2*)(r1p + 8);
            uint4 ah, al;
            split2(p00.x, p00.y, ah.x, al.x);
            split2(p10.x, p10.y, ah.y, al.y);
            split2(p01.x, p01.y, ah.z, al.z);
            split2(p11.x, p11.y, ah.w, al.w);

            #pragma unroll
            for (int nt = 0; nt < 16; nt++) {
                uint4 b = ((const uint4*)smem)[(nt * 16 + ksl) * 32 + lane];
                mma_bf16(acc[nt], ah, b.x, b.y);   // ah * wh
                mma_bf16(acc[nt], ah, b.z, b.w);   // ah * wl
                mma_bf16(acc[nt], al, b.x, b.y);   // al * wh
            }
        }
    }

    // ---- epilogue ----
    #pragma unroll
    for (int nt = 0; nt < 16; nt++) {
        int n0 = nt * 8 + tg * 2;
        float b0 = s_bias[n0], b1 = s_bias[n0 + 1];
        acc[nt][0] += b0; acc[nt][1] += b1;
        acc[nt][2] += b0; acc[nt][3] += b1;
    }

    if (do_ln) {
        float s0 = 0.f, q0 = 0.f, s1 = 0.f, q1 = 0.f;
        #pragma unroll
        for (int nt = 0; nt < 16; nt++) {
            s0 += acc[nt][0] + acc[nt][1];
            q0 += acc[nt][0] * acc[nt][0] + acc[nt][1] * acc[nt][1];
            s1 += acc[nt][2] + acc[nt][3];
            q1 += acc[nt][2] * acc[nt][2] + acc[nt][3] * acc[nt][3];
        }
        #pragma unroll
        for (int o = 1; o <= 2; o <<= 1) {
            s0 += __shfl_xor_sync(0xffffffffu, s0, o);
            q0 += __shfl_xor_sync(0xffffffffu, q0, o);
            s1 += __shfl_xor_sync(0xffffffffu, s1, o);
            q1 += __shfl_xor_sync(0xffffffffu, q1, o);
        }
        float mu0 = s0 * (1.0f / H), mu1 = s1 * (1.0f / H);
        float rs0 = rsqrtf(q0 * (1.0f / H) - mu0 * mu0 + 1e-5f);
        float rs1 = rsqrtf(q1 * (1.0f / H) - mu1 * mu1 + 1e-5f);

        const float* xin = g_X[layer];
        float* xout = g_X[layer + 1];
        #pragma unroll
        for (int nt = 0; nt < 16; nt++) {
            int n0 = nt * 8 + tg * 2;
            float ga0 = s_gamma[n0], ga1 = s_gamma[n0 + 1];
            float be0 = s_beta[n0],  be1 = s_beta[n0 + 1];
            float2 o0, o1;
            o0.x = fmaxf((acc[nt][0] - mu0) * rs0 * ga0 + be0, 0.f);
            o0.y = fmaxf((acc[nt][1] - mu0) * rs0 * ga1 + be1, 0.f);
            o1.x = fmaxf((acc[nt][2] - mu1) * rs1 * ga0 + be0, 0.f);
            o1.y = fmaxf((acc[nt][3] - mu1) * rs1 * ga1 + be1, 0.f);
            if (layer > 0) {
                float2 r0 = *(const float2*)(xin + m0 * H + n0);
                float2 r1 = *(const float2*)(xin + m1 * H + n0);
                o0.x += r0.x; o0.y += r0.y;
                o1.x += r1.x; o1.y += r1.y;
            }
            *(float2*)(xout + m0 * H + n0) = o0;
            *(float2*)(xout + m1 * H + n0) = o1;
        }
    } else {
        bool w0 = m0 < (size_t)NNODES, w1 = m1 < (size_t)NNODES;
        #pragma unroll
        for (int nt = 0; nt < 16; nt++) {
            int n0 = nt * 8 + tg * 2;
            if (w0) *(float2*)(outp + m0 * H + n0) = make_float2(acc[nt][0], acc[nt][1]);
            if (w1) *(float2*)(outp + m1 * H + n0) = make_float2(acc[nt][2], acc[nt][3]);
        }
    }
}

// ---------------- launch ----------------
extern "C" void kernel_launch(void* const* d_in, const int* in_sizes, int n_in,
                              void* d_out, int out_size) {
    const float* emb = (const float*)d_in[0];
    const float* Wl  = (const float*)d_in[1];
    const float* bl  = (const float*)d_in[2];
    const float* Wr  = (const float*)d_in[3];
    const float* lg  = (const float*)d_in[4];
    const float* lb  = (const float*)d_in[5];
    const float* jkW = (const float*)d_in[6];
    const float* jkb = (const float*)d_in[7];
    const int*   ei  = (const int*)d_in[8];
    int E = in_sizes[8] / 2;
    const int* src = ei;
    const int* dst = ei + E;
    float* out = (float*)d_out;

    const int MMA_SMEM = 131072 + 3 * 128 * 4;   // W frags + bias/gamma/beta
    cudaFuncSetAttribute(k_mma, cudaFuncAttributeMaxDynamicSharedMemorySize, MMA_SMEM);

    k_zero_deg<<<(NP + 255) / 256, 256>>>();
    k_hist<<<(E + 255) / 256, 256>>>(dst, E);
    k_scan<<<1, 1024>>>();
    k_fill<<<(E + 255) / 256, 256>>>(src, dst, E);
    k_copy_emb<<<NP * (H / 4) / 256, 256>>>((const float4*)emb);
    k_conv_w<<<(5 * 16 * 16 * 32 + 255) / 256, 256>>>(Wl, Wr, jkW);

    for (int l = 0; l < 3; l++) {
        k_agg<<<NP / 8, 256>>>(l);
        k_mma<<<NP / 128, 256, MMA_SMEM>>>(16, l, 1, 1, l,
                                           bl + l * H, lg + l * H, lb + l * H, nullptr);
    }
    k_mma<<<NP / 128, 256, MMA_SMEM>>>(32, 3, 2, 0, 0, jkb, nullptr, nullptr, out);
}

// round 5
// speedup vs baseline: 1.2324x; 1.2324x over previous
#include <cuda_runtime.h>
#include <cuda_bf16.h>
#include <cstdint>

#define NNODES 100000
#define NP     100352            // multiple of 1024 and 128
#define H      128
#define EMAX   1600000
#define NT16   (NP / 16)         // 6272 fragment tiles

// ---------------- device scratch ----------------
__device__ float g_X[4][(size_t)NP * H];
__device__ int   g_deg[NP];
__device__ float g_invdeg[NP];
__device__ int   g_rowstart[NP + 1];
__device__ int   g_cursor[NP];
__device__ int   g_csrsrc[EMAX];
__device__ uint8_t g_wfrag[5 * 131072];                    // 3 layers + 2 JK phases
// A fragments, per source: [tile][ks 0..7][lane]*32B  (tile stride 8KB)
__device__ uint8_t g_fragAgg[(size_t)NT16 * 8192];
__device__ uint8_t g_fragX[4][(size_t)NT16 * 8192];

// ---------------- CSR build ----------------
__global__ void k_zero_deg() {
    int i = blockIdx.x * blockDim.x + threadIdx.x;
    if (i < NP) g_deg[i] = 0;
}
__global__ void k_hist(const int* __restrict__ dst, int E) {
    int i = blockIdx.x * blockDim.x + threadIdx.x;
    if (i < E) atomicAdd(&g_deg[dst[i]], 1);
}
__global__ void k_scan() {
    __shared__ int warp_tot[32];
    int t = threadIdx.x, lane = t & 31, wid = t >> 5;
    int running = 0;
    for (int base = 0; base < NP; base += 1024) {
        int v = g_deg[base + t];
        int x = v;
        #pragma unroll
        for (int d = 1; d < 32; d <<= 1) {
            int y = __shfl_up_sync(0xffffffffu, x, d);
            if (lane >= d) x += y;
        }
        if (lane == 31) warp_tot[wid] = x;
        __syncthreads();
        if (wid == 0) {
            int y = warp_tot[lane];
            #pragma unroll
            for (int d = 1; d < 32; d <<= 1) {
                int z = __shfl_up_sync(0xffffffffu, y, d);
                if (lane >= d) y += z;
            }
            warp_tot[lane] = y;
        }
        __syncthreads();
        int warp_off = (wid == 0) ? 0 : warp_tot[wid - 1];
        g_rowstart[base + t] = running + warp_off + x - v;
        int block_tot = warp_tot[31];
        __syncthreads();
        running += block_tot;
        g_invdeg[base + t] = 1.0f / fmaxf((float)v, 1.0f);
        g_cursor[base + t] = 0;
    }
    if (t == 0) g_rowstart[NP] = running;
}
__global__ void k_fill(const int* __restrict__ src, const int* __restrict__ dst, int E) {
    int i = blockIdx.x * blockDim.x + threadIdx.x;
    if (i < E) {
        int d = dst[i];
        int p = atomicAdd(&g_cursor[d], 1);
        g_csrsrc[g_rowstart[d] + p] = src[i];
    }
}

// ---------------- bf16 hi/lo split ----------------
__device__ __forceinline__ void split2(float v0, float v1, uint32_t& ph, uint32_t& pl) {
    __nv_bfloat16 h0 = __float2bfloat16(v0), h1 = __float2bfloat16(v1);
    float r0 = v0 - __bfloat162float(h0), r1 = v1 - __bfloat162float(h1);
    __nv_bfloat16 l0 = __float2bfloat16(r0), l1 = __float2bfloat16(r1);
    ph = ((uint32_t)__bfloat16_as_ushort(h1) << 16) | (uint32_t)__bfloat16_as_ushort(h0);
    pl = ((uint32_t)__bfloat16_as_ushort(l1) << 16) | (uint32_t)__bfloat16_as_ushort(l0);
}

// Convert one smem-staged 16x128 tile (row stride SROW floats) to frag layout.
// Caller: threads with cid in [0,256): ks = cid>>5, lane = cid&31.
#define SROW 132
__device__ __forceinline__ void smem_tile_to_frag(const float* s_tile, uint8_t* fragdst,
                                                  int tile, int cid) {
    int ks = cid >> 5, lane = cid & 31;
    int g = lane >> 2, tg = lane & 3;
    const float* rA = s_tile + g * SROW;
    const float* rB = s_tile + (g + 8) * SROW;
    int c = ks * 16 + tg * 2;
    float2 p00 = make_float2(rA[c], rA[c + 1]);
    float2 p10 = make_float2(rB[c], rB[c + 1]);
    float2 p01 = make_float2(rA[c + 8], rA[c + 9]);
    float2 p11 = make_float2(rB[c + 8], rB[c + 9]);
    uint4 ah, al;
    split2(p00.x, p00.y, ah.x, al.x);
    split2(p10.x, p10.y, ah.y, al.y);
    split2(p01.x, p01.y, ah.z, al.z);
    split2(p11.x, p11.y, ah.w, al.w);
    uint4* fd = (uint4*)(fragdst + ((size_t)(tile * 8 + ks) * 32 + lane) * 32);
    fd[0] = ah; fd[1] = al;
}

// ---------------- emb: float copy + frag conversion (one-time) ----------------
__global__ void __launch_bounds__(256) k_emb_frag(const float* __restrict__ emb) {
    __shared__ float s_tile[16 * SROW];
    int tid = threadIdx.x;
    int tile = blockIdx.x;
    size_t rowBase = (size_t)tile * 16;
    // stage 16x128 floats (zero-pad rows >= NNODES), also write g_X[0]
    #pragma unroll
    for (int i = 0; i < 2; i++) {
        int idx = tid + i * 256;               // 0..511 float4 slots
        int r = idx >> 5, c4 = idx & 31;
        size_t row = rowBase + r;
        float4 v = make_float4(0.f, 0.f, 0.f, 0.f);
        if (row < (size_t)NNODES) v = ((const float4*)(emb + row * H))[c4];
        *(float4*)(s_tile + r * SROW + c4 * 4) = v;
        ((float4*)(g_X[0] + row * H))[c4] = v;
    }
    __syncthreads();
    smem_tile_to_frag(s_tile, g_fragX[0], tile, tid);
}

// ---------------- aggregation: 16 warps/block = 1 frag tile; emit frags directly ----------------
__global__ void __launch_bounds__(512) k_agg(int layer) {
    __shared__ float s_tile[16 * SROW];
    int tid = threadIdx.x, w = tid >> 5, lane = tid & 31;
    int tile = blockIdx.x;
    int node = tile * 16 + w;
    const float* __restrict__ xin = g_X[layer];
    int s0 = g_rowstart[node], s1 = g_rowstart[node + 1];
    float ax = 0.f, ay = 0.f, az = 0.f, aw = 0.f;
    int j = s0;
    for (; j + 4 <= s1; j += 4) {
        int i0 = g_csrsrc[j], i1 = g_csrsrc[j + 1], i2 = g_csrsrc[j + 2], i3 = g_csrsrc[j + 3];
        float4 a = ((const float4*)(xin + (size_t)i0 * H))[lane];
        float4 b = ((const float4*)(xin + (size_t)i1 * H))[lane];
        float4 c = ((const float4*)(xin + (size_t)i2 * H))[lane];
        float4 d = ((const float4*)(xin + (size_t)i3 * H))[lane];
        ax += (a.x + b.x) + (c.x + d.x);
        ay += (a.y + b.y) + (c.y + d.y);
        az += (a.z + b.z) + (c.z + d.z);
        aw += (a.w + b.w) + (c.w + d.w);
    }
    for (; j < s1; j++) {
        int i0 = g_csrsrc[j];
        float4 a = ((const float4*)(xin + (size_t)i0 * H))[lane];
        ax += a.x; ay += a.y; az += a.z; aw += a.w;
    }
    float inv = g_invdeg[node];
    *(float4*)(s_tile + w * SROW + lane * 4) = make_float4(ax * inv, ay * inv, az * inv, aw * inv);
    __syncthreads();
    if (tid < 256) smem_tile_to_frag(s_tile, g_fragAgg, tile, tid);
}

// ---------------- W fragment build ----------------
// target t: 0..2 = layer (k<128: Wl, k>=128: Wr), 3..4 = jk phase
__global__ void k_conv_w(const float* __restrict__ Wl, const float* __restrict__ Wr,
                         const float* __restrict__ jkW) {
    int idx = blockIdx.x * blockDim.x + threadIdx.x;
    if (idx >= 5 * 16 * 16 * 32) return;
    int lane = idx & 31;
    int ks = (idx >> 5) & 15;
    int nt = (idx >> 9) & 15;
    int tgt = idx >> 13;
    int g = lane >> 2, tg = lane & 3;
    int n = nt * 8 + g;
    int k = ks * 16 + tg * 2;

    float v[4];
    if (tgt < 3) {
        #pragma unroll
        for (int q = 0; q < 4; q++) {
            int kk = k + (q >> 1) * 8 + (q & 1);
            v[q] = (kk < 128) ? Wl[(size_t)tgt * 16384 + n * 128 + kk]
                              : Wr[(size_t)tgt * 16384 + n * 128 + kk - 128];
        }
    } else {
        int h = tgt - 3;
        #pragma unroll
        for (int q = 0; q < 4; q++) {
            int kk = k + (q >> 1) * 8 + (q & 1);
            v[q] = jkW[(size_t)n * 512 + h * 256 + kk];
        }
    }
    uint32_t bh0, bl0, bh1, bl1;
    split2(v[0], v[1], bh0, bl0);
    split2(v[2], v[3], bh1, bl1);
    *(uint4*)(g_wfrag + (size_t)tgt * 131072 + ((size_t)((nt * 16 + ks) * 32 + lane)) * 16)
        = make_uint4(bh0, bh1, bl0, bl1);
}

// ---------------- mma helper ----------------
__device__ __forceinline__ void mma_bf16(float* c, uint4 a, uint32_t b0, uint32_t b1) {
    asm volatile(
        "mma.sync.aligned.m16n8k16.row.col.f32.bf16.bf16.f32 "
        "{%0,%1,%2,%3}, {%4,%5,%6,%7}, {%8,%9}, {%0,%1,%2,%3};"
        : "+f"(c[0]), "+f"(c[1]), "+f"(c[2]), "+f"(c[3])
        : "r"(a.x), "r"(a.y), "r"(a.z), "r"(a.w), "r"(b0), "r"(b1));
}

// ---------------- GEMM + fused epilogue (LN/ReLU/residual + frag emit) ----------------
// grid NP/128, 256 threads (8 warps); warp = 16 rows x 128 cols.
// do_ln=1: layer l (A = frag(agg)|frag(X[l]), writes X[l+1] floats (l<2) + frag_X[l+1])
// do_ln=0: JK (A = frag(X0..X3), 2 phases, bias only, store to outp)
__global__ void __launch_bounds__(256, 1) k_mma(
    int wtgt0, int nphase, int do_ln, int layer,
    const float* __restrict__ bias, const float* __restrict__ gamma,
    const float* __restrict__ beta, float* __restrict__ outp)
{
    extern __shared__ uint8_t smem[];
    float* s_bias  = (float*)(smem + 131072);
    float* s_gamma = s_bias + 128;
    float* s_beta  = s_gamma + 128;
    int tid = threadIdx.x, wid = tid >> 5, lane = tid & 31;
    int g = lane >> 2, tg = lane & 3;
    int mt = blockIdx.x * 8 + wid;
    size_t m0 = (size_t)mt * 16 + g, m1 = m0 + 8;

    if (tid < 128) {
        s_bias[tid] = bias[tid];
        if (do_ln) { s_gamma[tid] = gamma[tid]; s_beta[tid] = beta[tid]; }
    }

    float acc[16][4];
    #pragma unroll
    for (int nt = 0; nt < 16; nt++)
        #pragma unroll
        for (int q = 0; q < 4; q++) acc[nt][q] = 0.f;

    for (int ph = 0; ph < nphase; ph++) {
        __syncthreads();
        {   // copy W fragment blob to smem (128KB)
            const uint4* wsrc = (const uint4*)(g_wfrag + (size_t)(wtgt0 + ph) * 131072);
            uint4* wdst = (uint4*)smem;
            #pragma unroll
            for (int i = 0; i < 32; i++) wdst[tid + i * 256] = wsrc[tid + i * 256];
        }
        __syncthreads();
        for (int ksl = 0; ksl < 16; ksl++) {
            int gks = ph * 16 + ksl;
            const uint8_t* asrc;
            int kloc;
            if (do_ln) {
                if (gks < 8) { asrc = g_fragAgg;      kloc = gks; }
                else         { asrc = g_fragX[layer]; kloc = gks - 8; }
            } else {
                asrc = g_fragX[gks >> 3]; kloc = gks & 7;
            }
            const uint4* ap = (const uint4*)(asrc + ((size_t)(mt * 8 + kloc) * 32 + lane) * 32);
            uint4 ah = ap[0], al = ap[1];
            #pragma unroll
            for (int nt = 0; nt < 16; nt++) {
                uint4 b = ((const uint4*)smem)[(nt * 16 + ksl) * 32 + lane];
                mma_bf16(acc[nt], ah, b.x, b.y);   // ah * wh
                mma_bf16(acc[nt], ah, b.z, b.w);   // ah * wl
                mma_bf16(acc[nt], al, b.x, b.y);   // al * wh
            }
        }
    }

    // ---- epilogue ----
    #pragma unroll
    for (int nt = 0; nt < 16; nt++) {
        int n0 = nt * 8 + tg * 2;
        float b0 = s_bias[n0], b1 = s_bias[n0 + 1];
        acc[nt][0] += b0; acc[nt][1] += b1;
        acc[nt][2] += b0; acc[nt][3] += b1;
    }

    if (do_ln) {
        float s0 = 0.f, q0 = 0.f, s1 = 0.f, q1 = 0.f;
        #pragma unroll
        for (int nt = 0; nt < 16; nt++) {
            s0 += acc[nt][0] + acc[nt][1];
            q0 += acc[nt][0] * acc[nt][0] + acc[nt][1] * acc[nt][1];
            s1 += acc[nt][2] + acc[nt][3];
            q1 += acc[nt][2] * acc[nt][2] + acc[nt][3] * acc[nt][3];
        }
        #pragma unroll
        for (int o = 1; o <= 2; o <<= 1) {
            s0 += __shfl_xor_sync(0xffffffffu, s0, o);
            q0 += __shfl_xor_sync(0xffffffffu, q0, o);
            s1 += __shfl_xor_sync(0xffffffffu, s1, o);
            q1 += __shfl_xor_sync(0xffffffffu, q1, o);
        }
        float mu0 = s0 * (1.0f / H), mu1 = s1 * (1.0f / H);
        float rs0 = rsqrtf(q0 * (1.0f / H) - mu0 * mu0 + 1e-5f);
        float rs1 = rsqrtf(q1 * (1.0f / H) - mu1 * mu1 + 1e-5f);

        const float* xin = g_X[layer];
        float* xout = g_X[layer + 1];
        uint8_t* fragout = g_fragX[layer + 1];
        bool wr_float = (layer < 2);                 // X3 floats are never read
        #pragma unroll
        for (int ks2 = 0; ks2 < 8; ks2++) {
            float2 oa0, oa1, ob0, ob1;               // a: nt=2ks2, b: nt=2ks2+1
            #pragma unroll
            for (int half = 0; half < 2; half++) {
                int nt = 2 * ks2 + half;
                int n0 = nt * 8 + tg * 2;
                float ga0 = s_gamma[n0], ga1 = s_gamma[n0 + 1];
                float be0 = s_beta[n0],  be1 = s_beta[n0 + 1];
                float2 o0, o1;
                o0.x = fmaxf((acc[nt][0] - mu0) * rs0 * ga0 + be0, 0.f);
                o0.y = fmaxf((acc[nt][1] - mu0) * rs0 * ga1 + be1, 0.f);
                o1.x = fmaxf((acc[nt][2] - mu1) * rs1 * ga0 + be0, 0.f);
                o1.y = fmaxf((acc[nt][3] - mu1) * rs1 * ga1 + be1, 0.f);
                if (layer > 0) {
                    float2 r0 = *(const float2*)(xin + m0 * H + n0);
                    float2 r1 = *(const float2*)(xin + m1 * H + n0);
                    o0.x += r0.x; o0.y += r0.y;
                    o1.x += r1.x; o1.y += r1.y;
                }
                if (wr_float) {
                    *(float2*)(xout + m0 * H + n0) = o0;
                    *(float2*)(xout + m1 * H + n0) = o1;
                }
                if (half == 0) { oa0 = o0; oa1 = o1; }
                else           { ob0 = o0; ob1 = o1; }
            }
            uint4 ah, al;
            split2(oa0.x, oa0.y, ah.x, al.x);
            split2(oa1.x, oa1.y, ah.y, al.y);
            split2(ob0.x, ob0.y, ah.z, al.z);
            split2(ob1.x, ob1.y, ah.w, al.w);
            uint4* fd = (uint4*)(fragout + ((size_t)(mt * 8 + ks2) * 32 + lane) * 32);
            fd[0] = ah; fd[1] = al;
        }
    } else {
        bool w0 = m0 < (size_t)NNODES, w1 = m1 < (size_t)NNODES;
        #pragma unroll
        for (int nt = 0; nt < 16; nt++) {
            int n0 = nt * 8 + tg * 2;
            if (w0) *(float2*)(outp + m0 * H + n0) = make_float2(acc[nt][0], acc[nt][1]);
            if (w1) *(float2*)(outp + m1 * H + n0) = make_float2(acc[nt][2], acc[nt][3]);
        }
    }
}

// ---------------- launch ----------------
extern "C" void kernel_launch(void* const* d_in, const int* in_sizes, int n_in,
                              void* d_out, int out_size) {
    const float* emb = (const float*)d_in[0];
    const float* Wl  = (const float*)d_in[1];
    const float* bl  = (const float*)d_in[2];
    const float* Wr  = (const float*)d_in[3];
    const float* lg  = (const float*)d_in[4];
    const float* lb  = (const float*)d_in[5];
    const float* jkW = (const float*)d_in[6];
    const float* jkb = (const float*)d_in[7];
    const int*   ei  = (const int*)d_in[8];
    int E = in_sizes[8] / 2;
    const int* src = ei;
    const int* dst = ei + E;
    float* out = (float*)d_out;

    const int MMA_SMEM = 131072 + 3 * 128 * 4;
    cudaFuncSetAttribute(k_mma, cudaFuncAttributeMaxDynamicSharedMemorySize, MMA_SMEM);

    k_zero_deg<<<(NP + 255) / 256, 256>>>();
    k_hist<<<(E + 255) / 256, 256>>>(dst, E);
    k_scan<<<1, 1024>>>();
    k_fill<<<(E + 255) / 256, 256>>>(src, dst, E);
    k_emb_frag<<<NT16, 256>>>(emb);
    k_conv_w<<<(5 * 16 * 16 * 32 + 255) / 256, 256>>>(Wl, Wr, jkW);

    for (int l = 0; l < 3; l++) {
        k_agg<<<NT16, 512>>>(l);
        k_mma<<<NP / 128, 256, MMA_SMEM>>>(l, 1, 1, l,
                                           bl + l * H, lg + l * H, lb + l * H, nullptr);
    }
    k_mma<<<NP / 128, 256, MMA_SMEM>>>(3, 2, 0, 0, jkb, nullptr, nullptr, out);
}